// round 17
// baseline (speedup 1.0000x reference)
#include <cuda_runtime.h>
#include <cuda_fp16.h>
#include <math.h>
#include <stdint.h>

// Problem dims
#define BB   64
#define TT   2048
#define ENC  512
#define DEC  512
#define UU   128
#define BT   (BB*TT)

// Tiling — A-only smem stages; B comes straight from the gmem fragment table
#define ASTRIDE     40                    // fp32 per A smem row (32 + 8 pad) — conflict-free
#define A_BYTES     (128 * ASTRIDE * 4)   // 20480
#define A_FLOATS    (128 * ASTRIDE)
#define BCH_BYTES   8192                  // permuted B fragment table per chunk (gmem)
#define STAGE_BYTES A_BYTES
#define STAGE_FLOATS (STAGE_BYTES / 4)
#define NSTAGE      4
#define DYN_BYTES   (NSTAGE * STAGE_BYTES + 1024)   // ~83 KB

#define NSPLIT 16                         // T-sixteenths per batch (1 tile each)
#define NCTA   (BB * NSPLIT)              // 1024 CTAs
#define NCHUNKS_TOTAL 16                  // k-chunks per tile

// scratch (__device__ globals per allocation-free rule)
__device__ float    g_q_part[4][BB * UU]; // e-quarter partials of q
__device__ uint32_t g_WbF[16 * 2 * 8 * 32 * 4];  // fragment-permuted Wb (128 KB)
__device__ float    g_ctx_part[NCTA * ENC];      // 2 MB
__device__ float    g_l_part[NCTA];
__device__ int      g_cnt[BB];            // zero-init; reset after use each launch

// ---------------------------------------------------------------------------
// helpers
// ---------------------------------------------------------------------------
__device__ __forceinline__ uint32_t smem_u32(const void* p) {
    uint32_t a;
    asm("{ .reg .u64 t; cvta.to.shared.u64 t, %1; cvt.u32.u64 %0, t; }"
        : "=r"(a) : "l"(p));
    return a;
}
__device__ __forceinline__ void cpy16(uint32_t dst, const void* src) {
    asm volatile("cp.async.cg.shared.global [%0], [%1], 16;"
                 :: "r"(dst), "l"(src) : "memory");
}
__device__ __forceinline__ void cp_commit() {
    asm volatile("cp.async.commit_group;" ::: "memory");
}
__device__ __forceinline__ void cp_wait2() {
    asm volatile("cp.async.wait_group 2;" ::: "memory");
}
__device__ __forceinline__ float tanh_approx(float x) {
    float y; asm("tanh.approx.f32 %0, %1;" : "=f"(y) : "f"(x));
    return y;
}
__device__ __forceinline__ uint32_t packh2(float lo, float hi) {
    __half2 h = __float22half2_rn(make_float2(lo, hi));
    return *(uint32_t*)&h;
}
__device__ __forceinline__ void mma_f16(float* c, const uint32_t* a,
                                        const uint32_t* b) {
    asm volatile(
        "mma.sync.aligned.m16n8k16.row.col.f32.f16.f16.f32 "
        "{%0,%1,%2,%3}, {%4,%5,%6,%7}, {%8,%9}, {%0,%1,%2,%3};\n"
        : "+f"(c[0]), "+f"(c[1]), "+f"(c[2]), "+f"(c[3])
        : "r"(a[0]), "r"(a[1]), "r"(a[2]), "r"(a[3]),
          "r"(b[0]), "r"(b[1]));
}

// ---------------------------------------------------------------------------
// K0: prep, 512 threads/block.
//   Blocks 0..255:   q partials. block = (b, eq of 4); threads (u, eg of 4):
//                    chain length 32; smem reduce -> g_q_part[eq][b][u].
//   Blocks 256..271: fragment-permuted B table (verified R15/R16 mapping).
// ---------------------------------------------------------------------------
__global__ void prep_kernel(const float* __restrict__ dh,
                            const float* __restrict__ Wa,
                            const float* __restrict__ ba,
                            const float* __restrict__ bb,
                            const float* __restrict__ Wb) {
    if (blockIdx.x < 4 * BB) {
        __shared__ float part[512];
        const int b  = blockIdx.x >> 2;
        const int eq = blockIdx.x & 3;
        const int u  = threadIdx.x & 127;
        const int eg = threadIdx.x >> 7;          // 0..3
        const int e0 = eq * 128 + eg * 32;
        float acc = 0.f;
        const float* dhb = dh + b * DEC + e0;
        const float* wap = Wa + (size_t)e0 * UU + u;
        #pragma unroll
        for (int e = 0; e < 32; e++)
            acc = fmaf(dhb[e], wap[(size_t)e * UU], acc);
        part[threadIdx.x] = acc;
        __syncthreads();
        if (threadIdx.x < 128) {
            float q = part[threadIdx.x] + part[threadIdx.x + 128]
                    + part[threadIdx.x + 256] + part[threadIdx.x + 384];
            if (eq == 0) q += ba[u] + bb[u];
            g_q_part[eq][b * UU + u] = q;
        }
    } else {
        const int s = (blockIdx.x - 4 * BB) * 512 + threadIdx.x;   // 0..8191
        const int lane = s & 31;
        const int nf   = (s >> 5) & 7;
        const int wn   = (s >> 8) & 1;
        const int c    = s >> 9;
        const int n  = wn * 64 + nf * 8 + (lane >> 2);
        const int kb = c * 32 + (lane & 3) * 2;
        uint4 v;
        v.x = packh2(Wb[(size_t)kb * UU + n],        Wb[(size_t)(kb + 1) * UU + n]);
        v.y = packh2(Wb[(size_t)(kb + 8) * UU + n],  Wb[(size_t)(kb + 9) * UU + n]);
        v.z = packh2(Wb[(size_t)(kb + 16) * UU + n], Wb[(size_t)(kb + 17) * UU + n]);
        v.w = packh2(Wb[(size_t)(kb + 24) * UU + n], Wb[(size_t)(kb + 25) * UU + n]);
        *(uint4*)&g_WbF[(size_t)s * 4] = v;
    }
}

// ---------------------------------------------------------------------------
// K1 (fused): CTA = (b, sixteenth) -> one 128-row tile, 16 k-chunks.
//   4-stage A-only cp.async pipeline (distance 3), mma.sync fp16 k16
//   (warp grid 4Mx2N), B frags via LDG.128 from the L2-hot fragment table,
//   fused tanh/exp epilogue, float4 context pass, last-CTA combine+normalize.
// ---------------------------------------------------------------------------
extern __shared__ float dynsmem[];

__global__ void __launch_bounds__(256, 2)
fused_kernel(const float* __restrict__ E,
             const float* __restrict__ Wv,
             const float* __restrict__ bv,
             float* __restrict__ ctx_out,
             float* __restrict__ attn_out) {
    __shared__ float  q_s[UU], wv_s[UU];
    __shared__ float  p_tile[128];
    __shared__ float  s_red[128][3];
    __shared__ float4 ctx_red[256];
    __shared__ int    is_last;

    const int tid  = threadIdx.x;
    const int lane = tid & 31;
    const int wid  = tid >> 5;
    const int wm   = wid >> 1;           // 0..3  (M quarter: 32 rows)
    const int wn   = wid & 1;            // 0..1  (N half: 64 cols)
    const int b    = blockIdx.x >> 4;
    const int six  = blockIdx.x & 15;
    const size_t rowbase = (size_t)b * TT + (size_t)six * 128;
    const float* Ebt = E + rowbase * ENC;

    const uint32_t dynb = (smem_u32(dynsmem) + 1023) & ~1023u;
    const int dynoff = (int)(dynb - smem_u32(dynsmem)) >> 2;

    if (tid < UU) {
        q_s[tid]  = g_q_part[0][b * UU + tid] + g_q_part[1][b * UU + tid]
                  + g_q_part[2][b * UU + tid] + g_q_part[3][b * UU + tid];
        wv_s[tid] = Wv[tid];
    }
    const float bv0 = bv[0];

    // chunk loader: A tile only (128 x 32 fp32)
    auto load_chunk = [&](int c) {
        const uint32_t sb = dynb + (c % NSTAGE) * STAGE_BYTES;
        const float* Asrc = Ebt + c * 32;
        #pragma unroll
        for (int it = 0; it < 4; it++) {
            int idx = tid + it * 256;
            int r = idx >> 3, q = idx & 7;
            cpy16(sb + r * 160 + q * 16, Asrc + (size_t)r * ENC + q * 4);
        }
        cp_commit();
    };

    load_chunk(0);
    load_chunk(1);
    load_chunk(2);

    float acc[2][8][4];
    #pragma unroll
    for (int mf = 0; mf < 2; mf++)
        #pragma unroll
        for (int nf = 0; nf < 8; nf++)
            { acc[mf][nf][0]=0.f; acc[mf][nf][1]=0.f;
              acc[mf][nf][2]=0.f; acc[mf][nf][3]=0.f; }

    // B fragment table base (uint4 index): ((c*2+wn)*8+nf)*32 + lane
    const uint4* WbF4 = (const uint4*)g_WbF;
    const uint32_t b_idx_base = (uint32_t)(wn * 8 * 32 + lane);

    for (int c = 0; c < NCHUNKS_TOTAL; c++) {
        cp_wait2();            // chunk c resident (3 groups in flight max)
        __syncthreads();       // all warps done computing chunk c-1
        if (c + 3 < NCHUNKS_TOTAL) load_chunk(c + 3);
        else                       cp_commit();   // uniform group count

        const float* As = dynsmem + dynoff + (c % NSTAGE) * STAGE_FLOATS;

        // B fragments for the whole chunk: 8 LDG.128 from L2-hot table
        uint32_t bq[8][4];
        {
            const uint4* tb = WbF4 + (size_t)c * 512 + b_idx_base;
            #pragma unroll
            for (int nf = 0; nf < 8; nf++) {
                uint4 v = __ldg(tb + nf * 32);
                bq[nf][0] = v.x; bq[nf][1] = v.y;
                bq[nf][2] = v.z; bq[nf][3] = v.w;
            }
        }

        #pragma unroll
        for (int ks = 0; ks < 2; ks++) {
            const int kk = ks * 16;
            uint32_t af[2][4];
            #pragma unroll
            for (int mf = 0; mf < 2; mf++) {
                const float* ap = As
                    + (wm * 32 + mf * 16 + (lane >> 2)) * ASTRIDE
                    + kk + (lane & 3) * 2;
                float2 v0 = *(const float2*)(ap);
                float2 v1 = *(const float2*)(ap + 8 * ASTRIDE);
                float2 v2 = *(const float2*)(ap + 8);
                float2 v3 = *(const float2*)(ap + 8 * ASTRIDE + 8);
                af[mf][0] = packh2(v0.x, v0.y);
                af[mf][1] = packh2(v1.x, v1.y);
                af[mf][2] = packh2(v2.x, v2.y);
                af[mf][3] = packh2(v3.x, v3.y);
            }
            #pragma unroll
            for (int mf = 0; mf < 2; mf++)
                #pragma unroll
                for (int nf = 0; nf < 8; nf++)
                    mma_f16(acc[mf][nf], af[mf], &bq[nf][ks * 2]);
        }
    }

    // ================= epilogue: s = Wv . tanh(q + k) =================
    #pragma unroll
    for (int mf = 0; mf < 2; mf++) {
        #pragma unroll
        for (int h = 0; h < 2; h++) {
            float ps = 0.f;
            #pragma unroll
            for (int nf = 0; nf < 8; nf++) {
                const int u0 = wn * 64 + nf * 8 + 2 * (lane & 3);
                ps = fmaf(wv_s[u0],
                          tanh_approx(q_s[u0] + acc[mf][nf][2 * h]), ps);
                ps = fmaf(wv_s[u0 + 1],
                          tanh_approx(q_s[u0 + 1] + acc[mf][nf][2 * h + 1]), ps);
            }
            ps += __shfl_xor_sync(0xffffffffu, ps, 1);
            ps += __shfl_xor_sync(0xffffffffu, ps, 2);
            if ((lane & 3) == 0) {
                const int row = wm * 32 + mf * 16 + (lane >> 2) + 8 * h;
                s_red[row][wn] = ps;
            }
        }
    }
    __syncthreads();
    if (tid < 128) {
        const float s = s_red[tid][0] + s_red[tid][1];
        const float p = __expf(s + bv0);
        p_tile[tid] = p;
        attn_out[rowbase + tid] = p;
    }
    __syncthreads();

    // l via warp-0 shuffle reduce
    if (wid == 0) {
        float pl = p_tile[lane] + p_tile[lane + 32]
                 + p_tile[lane + 64] + p_tile[lane + 96];
        #pragma unroll
        for (int off = 16; off > 0; off >>= 1)
            pl += __shfl_xor_sync(0xffffffffu, pl, off);
        if (lane == 0) g_l_part[blockIdx.x] = pl;
    }

    // context accumulation (E re-read, L2-hot): float4, row-halved
    {
        const int ehalf = tid >> 7;            // row half (0/1)
        const int e4    = tid & 127;           // float4 column index
        const float4* E4 = (const float4*)Ebt; // row stride 128 float4
        float4 cacc = make_float4(0.f, 0.f, 0.f, 0.f);
        #pragma unroll 8
        for (int t = 0; t < 64; t++) {
            const int row = ehalf * 64 + t;
            const float pt = p_tile[row];
            const float4 v = E4[(size_t)row * 128 + e4];
            cacc.x = fmaf(pt, v.x, cacc.x);
            cacc.y = fmaf(pt, v.y, cacc.y);
            cacc.z = fmaf(pt, v.z, cacc.z);
            cacc.w = fmaf(pt, v.w, cacc.w);
        }
        ctx_red[tid] = cacc;
    }
    __syncthreads();
    if (tid < 128) {
        const float4 a = ctx_red[tid];
        const float4 c2 = ctx_red[tid + 128];
        float4 r = make_float4(a.x + c2.x, a.y + c2.y, a.z + c2.z, a.w + c2.w);
        ((float4*)(g_ctx_part + (size_t)blockIdx.x * ENC))[tid] = r;
    }
    __syncthreads();          // all partial writes issued

    // ============ last-CTA-per-batch combine + normalize ============
    if (tid == 0) {
        __threadfence();       // publish partials + attn numerators
        const int old = atomicAdd(&g_cnt[b], 1);
        is_last = (old == NSPLIT - 1);
    }
    __syncthreads();
    if (is_last) {
        __threadfence();       // acquire other CTAs' writes
        float l = 0.f;
        #pragma unroll
        for (int s = 0; s < NSPLIT; s++) l += g_l_part[b * NSPLIT + s];
        const float linv = 1.f / l;
        #pragma unroll
        for (int i = 0; i < 2; i++) {
            const int e = tid + i * 256;
            float cacc = 0.f;
            #pragma unroll
            for (int s = 0; s < NSPLIT; s++)
                cacc += g_ctx_part[(size_t)(b * NSPLIT + s) * ENC + e];
            ctx_out[b * ENC + e] = cacc * linv;
        }
        #pragma unroll
        for (int i = 0; i < 8; i++)
            attn_out[(size_t)b * TT + tid + i * 256] *= linv;
        if (tid == 0) g_cnt[b] = 0;   // reset for next launch (idempotent)
    }
}

// ---------------------------------------------------------------------------
extern "C" void kernel_launch(void* const* d_in, const int* in_sizes, int n_in,
                              void* d_out, int out_size) {
    const float* dh = (const float*)d_in[0];
    const float* E  = (const float*)d_in[1];
    const float* Wa = (const float*)d_in[2];
    const float* ba = (const float*)d_in[3];
    const float* Wb = (const float*)d_in[4];
    const float* bb = (const float*)d_in[5];
    const float* Wv = (const float*)d_in[6];
    const float* bv = (const float*)d_in[7];

    float* out      = (float*)d_out;
    float* ctx_out  = out;                 // [64,512]
    float* attn_out = out + BB * ENC;      // [64,2048]

    cudaFuncSetAttribute(fused_kernel,
                         cudaFuncAttributeMaxDynamicSharedMemorySize, DYN_BYTES);

    prep_kernel<<<4 * BB + 16, 512>>>(dh, Wa, ba, bb, Wb);
    fused_kernel<<<NCTA, 256, DYN_BYTES>>>(E, Wv, bv, ctx_out, attn_out);
}